// round 5
// baseline (speedup 1.0000x reference)
#include <cuda_runtime.h>
#include <cstdint>
#include <cstddef>

using ull = unsigned long long;

#define THREADS 576
#define NCH     256
#define CK      8
#define NSTAGE  (NCH / CK)          // 32
#define H       64
#define W       64
#define TH      16
#define TW      32
#define YROWS   (TH + 8)            // 24
#define YSTR    44                  // floats; conflict-free + 16B aligned rows
#define XSTR    36
#define YS_BUF  (CK * YROWS * YSTR) // 8448 floats
#define XS_BUF  (CK * TH * XSTR)    // 4608 floats
#define BUF_FLOATS (YS_BUF + XS_BUF)        // 13056
#define SMEM_BYTES (3 * BUF_FLOATS * 4)     // 156672 B (3-stage pipeline)

#define NYV (CK * YROWS * 10)       // 1920 vec4 y-loads per stage
#define NXV (CK * TH * 8)           // 1024 vec4 x-loads per stage

// ---- async copy helpers (zfill gives the zero-padded halo for free) ----
__device__ __forceinline__ void cp16(uint32_t dst, const float* src, int ok) {
    asm volatile("cp.async.cg.shared.global [%0], [%1], 16, %2;\n"
                 :: "r"(dst), "l"(src), "r"(ok ? 16 : 0));
}
__device__ __forceinline__ void cp_commit() { asm volatile("cp.async.commit_group;\n"); }
__device__ __forceinline__ void cp_wait1()  { asm volatile("cp.async.wait_group 1;\n"); }

// ---- packed f32x2 math (FFMA2 is PTX-only on sm_103a) ----
__device__ __forceinline__ void fma2(ull& acc, ull a, ull b) {
    asm("fma.rn.f32x2 %0, %1, %2, %0;" : "+l"(acc) : "l"(a), "l"(b));
}
__device__ __forceinline__ ull mul2(ull a, ull b) {
    ull d;
    asm("mul.rn.f32x2 %0, %1, %2;" : "=l"(d) : "l"(a), "l"(b));
    return d;
}

__global__ __launch_bounds__(THREADS)
void corr_kernel(const float* __restrict__ xg, const float* __restrict__ yg,
                 float* __restrict__ out) {
    extern __shared__ float sm[];

    const int tid  = threadIdx.x;
    const int bb   = blockIdx.x >> 3;          // batch
    const int tile = blockIdx.x & 7;           // 4 row-tiles x 2 col-tiles
    const int i0   = (tile >> 1) * TH;
    const int j0   = (tile & 1) * TW;

    const int wid  = tid >> 5;
    const int lane = tid & 31;
    const int di   = (wid < 9) ? wid : wid - 9;   // displacement row 0..8
    const int half = (wid < 9) ? 0 : 1;           // which 8-row half of the tile
    const int gi   = half * 8 + (lane >> 2);      // pixel row within tile 0..15
    const int jl   = (lane & 3) * 8;              // 8-wide pixel strip start

    const uint32_t sbase = (uint32_t)__cvta_generic_to_shared(sm);

    // 36 packed accumulators: acc[dj*4 + m] = pixels (jl+2m, jl+2m+1) at (di, dj)
    ull acc[36];
#pragma unroll
    for (int k = 0; k < 36; k++) acc[k] = 0ULL;

    // ---------------- stage loader ----------------
    auto load_stage = [&](int s, int buf) {
        const uint32_t yb = sbase + (uint32_t)(buf * BUF_FLOATS) * 4u;
        const uint32_t xb = yb + (uint32_t)YS_BUF * 4u;
        const float* ygs = yg + ((size_t)(bb * NCH + s * CK)) * (H * W);
        const float* xgs = xg + ((size_t)(bb * NCH + s * CK)) * (H * W);
#pragma unroll
        for (int k = 0; k < 4; k++) {
            if (k < 3 || tid < NYV - 3 * THREADS) {
                int idx = tid + k * THREADS;
                int cc  = idx / (YROWS * 10);
                int rem = idx - cc * (YROWS * 10);
                int r   = rem / 10;
                int q   = rem - r * 10;
                int gr  = i0 + r - 4;
                int gc  = j0 - 4 + 4 * q;
                int ok  = (gr >= 0) & (gr < H) & (gc >= 0) & (gc < W);
                const float* src = ygs + ((cc * H + (ok ? gr : 0)) * W + (ok ? gc : 0));
                cp16(yb + (uint32_t)((cc * YROWS + r) * YSTR + 4 * q) * 4u, src, ok);
            }
        }
#pragma unroll
        for (int k = 0; k < 2; k++) {
            if (k == 0 || tid < NXV - THREADS) {
                int idx = tid + k * THREADS;
                int cc  = idx >> 7;            // / (TH*8)
                int r   = (idx >> 3) & 15;
                int q   = idx & 7;
                const float* src = xgs + ((cc * H + i0 + r) * W + j0 + 4 * q);
                cp16(xb + (uint32_t)((cc * TH + r) * XSTR + 4 * q) * 4u, src, 1);
            }
        }
        cp_commit();
    };

    // ---------------- 3-stage pipeline ----------------
    load_stage(0, 0);
    load_stage(1, 1);

    const int ybt = (gi + di) * YSTR + jl;   // per-thread smem bases (floats)
    const int xbt = gi * XSTR + jl;

    int buf = 0, lbuf = 2;
#pragma unroll 1
    for (int s = 0; s < NSTAGE; s++) {
        cp_wait1();          // own groups <= s done (group s issued 2 stages ago)
        __syncthreads();     // all threads' group s visible; all reads of s-1 done
        if (s + 2 < NSTAGE) load_stage(s + 2, lbuf);   // writes (s-1)%3: now safe
        else cp_commit();                              // keep group accounting

        const float* ysb = sm + buf * BUF_FLOATS;
        const float* xsb = ysb + YS_BUF;

#pragma unroll
        for (int cc = 0; cc < CK; cc++) {
            const ulonglong2* xr = (const ulonglong2*)(xsb + cc * (TH * XSTR) + xbt);
            const ulonglong2* yr = (const ulonglong2*)(ysb + cc * (YROWS * YSTR) + ybt);

            ulonglong2 xa = xr[0], xc = xr[1];
            ull xp[4] = { xa.x, xa.y, xc.x, xc.y };

            ull w[8];
#pragma unroll
            for (int k = 0; k < 4; k++) {
                ulonglong2 u = yr[k];
                w[2 * k] = u.x; w[2 * k + 1] = u.y;
            }
            // odd-offset pairs sp[q] = { y[2q+1], y[2q+2] }
            ull sp[7];
#pragma unroll
            for (int q = 0; q < 7; q++) sp[q] = (w[q] >> 32) | (w[q + 1] << 32);

#pragma unroll
            for (int dj = 0; dj < 9; dj++) {
#pragma unroll
                for (int m = 0; m < 4; m++) {
                    const int o = 2 * m + dj;   // compile-time, max 14
                    fma2(acc[dj * 4 + m], xp[m], (o & 1) ? sp[o >> 1] : w[o >> 1]);
                }
            }
        }

        buf  = (buf == 2) ? 0 : buf + 1;
        lbuf = (lbuf == 2) ? 0 : lbuf + 1;
    }

    // ---------------- epilogue: scale by 1/C, store ----------------
    const uint32_t su = __float_as_uint(1.0f / 256.0f);
    const ull scl = ((ull)su << 32) | su;
#pragma unroll
    for (int dj = 0; dj < 9; dj++) {
        float* op = out + (((size_t)bb * 81 + di * 9 + dj) * H + (i0 + gi)) * W
                        + j0 + jl;
        ulonglong2 v0, v1;
        v0.x = mul2(acc[dj * 4 + 0], scl);
        v0.y = mul2(acc[dj * 4 + 1], scl);
        v1.x = mul2(acc[dj * 4 + 2], scl);
        v1.y = mul2(acc[dj * 4 + 3], scl);
        ((ulonglong2*)op)[0] = v0;
        ((ulonglong2*)op)[1] = v1;
    }
}

extern "C" void kernel_launch(void* const* d_in, const int* in_sizes, int n_in,
                              void* d_out, int out_size) {
    (void)in_sizes; (void)n_in; (void)out_size;
    const float* x = (const float*)d_in[0];
    const float* y = (const float*)d_in[1];
    cudaFuncSetAttribute(corr_kernel, cudaFuncAttributeMaxDynamicSharedMemorySize,
                         SMEM_BYTES);
    corr_kernel<<<16 * 8, THREADS, SMEM_BYTES>>>(x, y, (float*)d_out);
}

// round 8
// speedup vs baseline: 1.7376x; 1.7376x over previous
#include <cuda_runtime.h>
#include <cstdint>
#include <cstddef>

using ull = unsigned long long;

#define THREADS 576
#define NCH     256
#define CK      8
#define NSTAGE  (NCH / CK)          // 32
#define H       64
#define W       64
#define TH      16
#define TW      32
#define YROWS   (TH + 8)            // 24
#define YSTR    44                  // floats; conflict-free + 16B aligned rows
#define XSTR    36
#define YS_BUF  (CK * YROWS * YSTR) // 8448 floats
#define XS_BUF  (CK * TH * XSTR)    // 4608 floats
#define BUF_FLOATS (YS_BUF + XS_BUF)        // 13056
#define SMEM_BYTES (3 * BUF_FLOATS * 4)     // 156672 B (3-stage pipeline)

#define NYV (CK * YROWS * 10)       // 1920 vec4 y-loads per stage
#define NXV (CK * TH * 8)           // 1024 vec4 x-loads per stage

// ---- async copy helpers (zfill gives the zero-padded halo for free) ----
__device__ __forceinline__ void cp16(uint32_t dst, const float* src, int ok) {
    asm volatile("cp.async.cg.shared.global [%0], [%1], 16, %2;\n"
                 :: "r"(dst), "l"(src), "r"(ok ? 16 : 0));
}
__device__ __forceinline__ void cp_commit() { asm volatile("cp.async.commit_group;\n"); }
__device__ __forceinline__ void cp_wait1()  { asm volatile("cp.async.wait_group 1;\n"); }

// ---- packed f32x2 math (FFMA2 is PTX-only on sm_103a) ----
__device__ __forceinline__ void fma2(ull& acc, ull a, ull b) {
    asm("fma.rn.f32x2 %0, %1, %2, %0;" : "+l"(acc) : "l"(a), "l"(b));
}
__device__ __forceinline__ ull mul2(ull a, ull b) {
    ull d;
    asm("mul.rn.f32x2 %0, %1, %2;" : "=l"(d) : "l"(a), "l"(b));
    return d;
}
__device__ __forceinline__ ull shft(ull lo, ull hi) {
    // { lo.hi, hi.lo } : odd-offset f32 pair
    return (lo >> 32) | (hi << 32);
}

__global__ __launch_bounds__(THREADS, 1)
void corr_kernel(const float* __restrict__ xg, const float* __restrict__ yg,
                 float* __restrict__ out) {
    extern __shared__ float sm[];

    const int tid  = threadIdx.x;
    const int bb   = blockIdx.x >> 3;          // batch
    const int tile = blockIdx.x & 7;           // 4 row-tiles x 2 col-tiles
    const int i0   = (tile >> 1) * TH;
    const int j0   = (tile & 1) * TW;

    const int wid  = tid >> 5;
    const int lane = tid & 31;
    const int di   = (wid < 9) ? wid : wid - 9;   // displacement row 0..8
    const int half = (wid < 9) ? 0 : 1;           // which 8-row half of the tile
    const int gi   = half * 8 + (lane >> 2);      // pixel row within tile 0..15
    const int jl   = (lane & 3) * 8;              // 8-wide pixel strip start

    const uint32_t sbase = (uint32_t)__cvta_generic_to_shared(sm);

    // 36 packed accumulators: acc[dj*4 + m] = pixels (jl+2m, jl+2m+1) at (di, dj)
    ull acc[36];
#pragma unroll
    for (int k = 0; k < 36; k++) acc[k] = 0ULL;

    // ---------------- stage loader ----------------
    auto load_stage = [&](int s, int buf) {
        const uint32_t yb = sbase + (uint32_t)(buf * BUF_FLOATS) * 4u;
        const uint32_t xb = yb + (uint32_t)YS_BUF * 4u;
        const float* ygs = yg + ((size_t)(bb * NCH + s * CK)) * (H * W);
        const float* xgs = xg + ((size_t)(bb * NCH + s * CK)) * (H * W);
#pragma unroll
        for (int k = 0; k < 4; k++) {
            if (k < 3 || tid < NYV - 3 * THREADS) {
                int idx = tid + k * THREADS;
                int cc  = idx / (YROWS * 10);
                int rem = idx - cc * (YROWS * 10);
                int r   = rem / 10;
                int q   = rem - r * 10;
                int gr  = i0 + r - 4;
                int gc  = j0 - 4 + 4 * q;
                int ok  = (gr >= 0) & (gr < H) & (gc >= 0) & (gc < W);
                const float* src = ygs + ((cc * H + (ok ? gr : 0)) * W + (ok ? gc : 0));
                cp16(yb + (uint32_t)((cc * YROWS + r) * YSTR + 4 * q) * 4u, src, ok);
            }
        }
#pragma unroll
        for (int k = 0; k < 2; k++) {
            if (k == 0 || tid < NXV - THREADS) {
                int idx = tid + k * THREADS;
                int cc  = idx >> 7;            // / (TH*8)
                int r   = (idx >> 3) & 15;
                int q   = idx & 7;
                const float* src = xgs + ((cc * H + i0 + r) * W + j0 + 4 * q);
                cp16(xb + (uint32_t)((cc * TH + r) * XSTR + 4 * q) * 4u, src, 1);
            }
        }
        cp_commit();
    };

    // ---------------- 3-stage pipeline ----------------
    load_stage(0, 0);
    load_stage(1, 1);

    const int ybt = (gi + di) * YSTR + jl;   // per-thread smem bases (floats)
    const int xbt = gi * XSTR + jl;

    int buf = 0, lbuf = 2;
#pragma unroll 1
    for (int s = 0; s < NSTAGE; s++) {
        cp_wait1();          // own groups <= s done (group s issued 2 stages ago)
        __syncthreads();     // all threads' group s visible; all reads of s-1 done
        if (s + 2 < NSTAGE) load_stage(s + 2, lbuf);   // writes (s-1)%3: now safe
        else cp_commit();                              // keep group accounting

        const float* ysb = sm + buf * BUF_FLOATS;
        const float* xsb = ysb + YS_BUF;

#pragma unroll
        for (int cc = 0; cc < CK; cc++) {
            const ulonglong2* xr = (const ulonglong2*)(xsb + cc * (TH * XSTR) + xbt);
            const ulonglong2* yr = (const ulonglong2*)(ysb + cc * (YROWS * YSTR) + ybt);

            // Issue all shared loads up front (latency), but compute the
            // odd-offset pairs (sp) just-in-time inside the m-loop so their
            // live ranges stay short -> fits the 112-reg cap without spills.
            ulonglong2 u0 = yr[0], u1 = yr[1], u2 = yr[2], u3 = yr[3];
            ulonglong2 xa = xr[0], xc = xr[1];

            ull w[8] = { u0.x, u0.y, u1.x, u1.y, u2.x, u2.y, u3.x, u3.y };
            ull xp[4] = { xa.x, xa.y, xc.x, xc.y };
            ull sp[7];

#pragma unroll
            for (int m = 0; m < 4; m++) {
                if (m == 0) {
#pragma unroll
                    for (int q = 0; q < 4; q++) sp[q] = shft(w[q], w[q + 1]);
                } else {
                    sp[m + 3] = shft(w[m + 3], w[m + 4]);
                }
#pragma unroll
                for (int dj = 0; dj < 9; dj++) {
                    const int o = 2 * m + dj;   // compile-time, max 14
                    fma2(acc[dj * 4 + m], xp[m], (o & 1) ? sp[o >> 1] : w[o >> 1]);
                }
            }
        }

        buf  = (buf == 2) ? 0 : buf + 1;
        lbuf = (lbuf == 2) ? 0 : lbuf + 1;
    }

    // ---------------- epilogue: scale by 1/C, store ----------------
    const uint32_t su = __float_as_uint(1.0f / 256.0f);
    const ull scl = ((ull)su << 32) | su;
#pragma unroll
    for (int dj = 0; dj < 9; dj++) {
        float* op = out + (((size_t)bb * 81 + di * 9 + dj) * H + (i0 + gi)) * W
                        + j0 + jl;
        ulonglong2 v0, v1;
        v0.x = mul2(acc[dj * 4 + 0], scl);
        v0.y = mul2(acc[dj * 4 + 1], scl);
        v1.x = mul2(acc[dj * 4 + 2], scl);
        v1.y = mul2(acc[dj * 4 + 3], scl);
        ((ulonglong2*)op)[0] = v0;
        ((ulonglong2*)op)[1] = v1;
    }
}

extern "C" void kernel_launch(void* const* d_in, const int* in_sizes, int n_in,
                              void* d_out, int out_size) {
    (void)in_sizes; (void)n_in; (void)out_size;
    const float* x = (const float*)d_in[0];
    const float* y = (const float*)d_in[1];
    cudaFuncSetAttribute(corr_kernel, cudaFuncAttributeMaxDynamicSharedMemorySize,
                         SMEM_BYTES);
    corr_kernel<<<16 * 8, THREADS, SMEM_BYTES>>>(x, y, (float*)d_out);
}